// round 4
// baseline (speedup 1.0000x reference)
#include <cuda_runtime.h>
#include <cuda_bf16.h>

#define NN 50000
#define EE 800000
#define NB_N 196      // ceil(50000/256)
#define NB_E 3125     // 800000/256 exact

typedef unsigned long long u64;

// ---------------- f32x2 helpers (FFMA2 only reachable via PTX) ----------------
__device__ __forceinline__ void fma2(u64 &c, u64 a, u64 b){
    asm("fma.rn.f32x2 %0, %1, %2, %0;" : "+l"(c) : "l"(a), "l"(b));
}
__device__ __forceinline__ u64 pack2(float x, float y){
    u64 r; asm("mov.b64 %0, {%1, %2};" : "=l"(r) : "f"(x), "f"(y)); return r;
}
__device__ __forceinline__ float2 unpack2(u64 v){
    float2 r; asm("mov.b64 {%0, %1}, %2;" : "=f"(r.x), "=f"(r.y) : "l"(v)); return r;
}

// ---------------- scratch (__device__ globals; no allocation) ----------------
__device__ float g_node_pre[(size_t)NN*64];
__device__ float g_nf_logit[(size_t)NN*3];
__device__ float g_prevp[NN];
__device__ float g_agg[(size_t)NN*64];
__device__ float g_contrib[(size_t)EE*64];
__device__ float g_message[(size_t)EE*64];
__device__ float g_m[(size_t)EE*64];
__device__ float g_x[(size_t)EE*64];
__device__ float g_gi[(size_t)EE*192];
__device__ float g_gh[(size_t)EE*192];

// ---------------- per-node precompute ----------------
__global__ void __launch_bounds__(256) k_node(
    const float* __restrict__ prob, const float* __restrict__ seed,
    const float* __restrict__ W_node, const float* __restrict__ b_node,
    const float* __restrict__ W_init, const float* __restrict__ b_init,
    const float* __restrict__ W_out,  const float* __restrict__ b_out)
{
    __shared__ float Wi[4096];
    __shared__ float Wn0[64], Wn1[64], bn[64], bi[64], Wo[192], bo[3];
    int tid = threadIdx.x;
    for (int i=tid;i<4096;i+=256) Wi[i]=W_init[i];          // rows 0..63
    if (tid<64){ Wn0[tid]=W_node[tid]; Wn1[tid]=W_node[64+tid]; bn[tid]=b_node[tid]; bi[tid]=b_init[tid]; }
    for (int i=tid;i<192;i+=256) Wo[i]=W_out[192+i];        // rows 64..127
    if (tid<3) bo[tid]=b_out[tid];
    __syncthreads();
    int n = blockIdx.x*256 + tid;
    if (n >= NN) return;
    float p = prob[n], s = seed[n];
    u64 acc[32];
    #pragma unroll
    for (int j=0;j<32;j++) acc[j]=pack2(bi[2*j],bi[2*j+1]);
    float l0=bo[0], l1=bo[1], l2=bo[2];
    #pragma unroll 4
    for (int k=0;k<64;k++){
        float nf = fmaxf(fmaf(p,Wn0[k],fmaf(s,Wn1[k],bn[k])), 0.f);
        u64 x2 = pack2(nf,nf);
        const ulonglong2* wr = (const ulonglong2*)&Wi[k*64];
        #pragma unroll
        for (int q=0;q<16;q++){ ulonglong2 w=wr[q]; fma2(acc[2*q],x2,w.x); fma2(acc[2*q+1],x2,w.y); }
        l0 = fmaf(nf,Wo[k*3],l0); l1 = fmaf(nf,Wo[k*3+1],l1); l2 = fmaf(nf,Wo[k*3+2],l2);
    }
    float4* outp = (float4*)&g_node_pre[(size_t)n*64];
    #pragma unroll
    for (int q=0;q<16;q++){ float2 a=unpack2(acc[2*q]); float2 b=unpack2(acc[2*q+1]); outp[q]=make_float4(a.x,a.y,b.x,b.y); }
    g_nf_logit[n*3]=l0; g_nf_logit[n*3+1]=l1; g_nf_logit[n*3+2]=l2;
}

// ---------------- per-edge init: message + contrib, scatter message ----------------
__global__ void __launch_bounds__(256) k_edge_init(
    const float* __restrict__ raw, const int* __restrict__ src, const int* __restrict__ tgt,
    const float* __restrict__ W_edge, const float* __restrict__ b_edge,
    const float* __restrict__ W_init, const float* __restrict__ W_me)
{
    __shared__ float Wi[4096], Wm[4096], we[64], be[64];
    int tid=threadIdx.x;
    for (int i=tid;i<4096;i+=256){ Wi[i]=W_init[4096+i]; Wm[i]=W_me[4096+i]; }
    if (tid<64){ we[tid]=W_edge[tid]; be[tid]=b_edge[tid]; }
    __syncthreads();
    size_t e = (size_t)blockIdx.x*256 + tid;
    float r = raw[e];
    // pass 1: message = relu(node_pre[src] + edge_feat @ Wi_bot)   (b_init inside node_pre)
    u64 acc[32];
    #pragma unroll
    for (int j=0;j<32;j++) acc[j]=pack2(0.f,0.f);
    #pragma unroll 4
    for (int k=0;k<64;k++){
        float ef = fmaxf(fmaf(r,we[k],be[k]), 0.f);
        u64 x2 = pack2(ef,ef);
        const ulonglong2* wr = (const ulonglong2*)&Wi[k*64];
        #pragma unroll
        for (int q=0;q<16;q++){ ulonglong2 w=wr[q]; fma2(acc[2*q],x2,w.x); fma2(acc[2*q+1],x2,w.y); }
    }
    {
        const float4* np = (const float4*)&g_node_pre[(size_t)src[e]*64];
        float4* msg = (float4*)&g_message[e*64];
        float* ag = &g_agg[(size_t)tgt[e]*64];
        #pragma unroll
        for (int q=0;q<16;q++){
            float2 a=unpack2(acc[2*q]), b=unpack2(acc[2*q+1]);
            float4 nv=np[q];
            float4 v=make_float4(fmaxf(a.x+nv.x,0.f),fmaxf(a.y+nv.y,0.f),fmaxf(b.x+nv.z,0.f),fmaxf(b.y+nv.w,0.f));
            msg[q]=v;
            atomicAdd(ag+4*q+0,v.x); atomicAdd(ag+4*q+1,v.y);
            atomicAdd(ag+4*q+2,v.z); atomicAdd(ag+4*q+3,v.w);
        }
    }
    // pass 2: contrib = edge_feat @ Wme_bot (no bias, no relu)
    #pragma unroll
    for (int j=0;j<32;j++) acc[j]=pack2(0.f,0.f);
    #pragma unroll 4
    for (int k=0;k<64;k++){
        float ef = fmaxf(fmaf(r,we[k],be[k]), 0.f);
        u64 x2 = pack2(ef,ef);
        const ulonglong2* wr = (const ulonglong2*)&Wm[k*64];
        #pragma unroll
        for (int q=0;q<16;q++){ ulonglong2 w=wr[q]; fma2(acc[2*q],x2,w.x); fma2(acc[2*q+1],x2,w.y); }
    }
    {
        float4* ctr = (float4*)&g_contrib[e*64];
        #pragma unroll
        for (int q=0;q<16;q++){ float2 a=unpack2(acc[2*q]); float2 b=unpack2(acc[2*q+1]); ctr[q]=make_float4(a.x,a.y,b.x,b.y); }
    }
}

#define SME_BYTES ((256*65 + 4096)*4)

// ---------------- m = relu(message @ W_me_top + contrib + b_me); scatter m by tgt ----------------
__global__ void __launch_bounds__(256) k_me(
    const float* __restrict__ W, const float* __restrict__ bias, const int* __restrict__ tgt)
{
    extern __shared__ float sm[];
    float* Xs = sm; float* Ws = sm + 256*65;
    __shared__ float bs[64];
    int tid=threadIdx.x;
    size_t base=(size_t)blockIdx.x*256;
    for (int i=tid;i<4096;i+=256) Ws[i]=W[i];           // rows 0..63
    if (tid<64) bs[tid]=bias[tid];
    for (int i=tid;i<16384;i+=256) Xs[((i>>6)*65)+(i&63)] = g_message[base*64+i];
    __syncthreads();
    u64 acc[32];
    #pragma unroll
    for (int j=0;j<32;j++) acc[j]=pack2(bs[2*j],bs[2*j+1]);
    const float* xr=&Xs[tid*65];
    #pragma unroll 4
    for (int k=0;k<64;k++){
        float xk=xr[k]; u64 x2=pack2(xk,xk);
        const ulonglong2* wr=(const ulonglong2*)&Ws[k*64];
        #pragma unroll
        for (int q=0;q<16;q++){ ulonglong2 w=wr[q]; fma2(acc[2*q],x2,w.x); fma2(acc[2*q+1],x2,w.y); }
    }
    size_t e=base+tid, eb=e*64;
    const float4* ct=(const float4*)&g_contrib[eb];
    float4* out=(float4*)&g_m[eb];
    float* ag=&g_agg[(size_t)tgt[e]*64];
    #pragma unroll
    for (int q=0;q<16;q++){
        float2 a=unpack2(acc[2*q]), b=unpack2(acc[2*q+1]);
        float4 c=ct[q];
        float4 v=make_float4(fmaxf(a.x+c.x,0.f),fmaxf(a.y+c.y,0.f),fmaxf(b.x+c.z,0.f),fmaxf(b.y+c.w,0.f));
        out[q]=v;
        atomicAdd(ag+4*q+0,v.x); atomicAdd(ag+4*q+1,v.y);
        atomicAdd(ag+4*q+2,v.z); atomicAdd(ag+4*q+3,v.w);
    }
}

// ---------------- x = relu((agg[src] - m[rev]) @ W_mp + b_mp) ----------------
__global__ void __launch_bounds__(256) k_mp(
    const float* __restrict__ W, const float* __restrict__ bias,
    const int* __restrict__ src, const int* __restrict__ rev)
{
    extern __shared__ float sm[];
    float* Xs = sm; float* Ws = sm + 256*65;
    __shared__ float bs[64];
    __shared__ int srcs[256], revs[256];
    int tid=threadIdx.x;
    size_t base=(size_t)blockIdx.x*256;
    srcs[tid]=src[base+tid]; revs[tid]=rev[base+tid];
    for (int i=tid;i<4096;i+=256) Ws[i]=W[i];
    if (tid<64) bs[tid]=bias[tid];
    __syncthreads();
    for (int i=tid;i<16384;i+=256){
        int el=i>>6, f=i&63;
        Xs[el*65+f] = g_agg[(size_t)srcs[el]*64+f] - g_m[(size_t)revs[el]*64+f];
    }
    __syncthreads();
    u64 acc[32];
    #pragma unroll
    for (int j=0;j<32;j++) acc[j]=pack2(bs[2*j],bs[2*j+1]);
    const float* xr=&Xs[tid*65];
    #pragma unroll 4
    for (int k=0;k<64;k++){
        float xk=xr[k]; u64 x2=pack2(xk,xk);
        const ulonglong2* wr=(const ulonglong2*)&Ws[k*64];
        #pragma unroll
        for (int q=0;q<16;q++){ ulonglong2 w=wr[q]; fma2(acc[2*q],x2,w.x); fma2(acc[2*q+1],x2,w.y); }
    }
    float4* out=(float4*)&g_x[(base+tid)*64];
    #pragma unroll
    for (int q=0;q<16;q++){
        float2 a=unpack2(acc[2*q]), b=unpack2(acc[2*q+1]);
        out[q]=make_float4(fmaxf(a.x,0.f),fmaxf(a.y,0.f),fmaxf(b.x,0.f),fmaxf(b.y,0.f));
    }
}

// ---------------- gate GEMM: Out[e, gb*64+c] = X[e] . W[(gb*64+c), :] + bias ----------------
// sel 0: X=g_x  -> g_gi ;  sel 1: X=g_message -> g_gh
__global__ void __launch_bounds__(256) k_gate(
    const float* __restrict__ W, const float* __restrict__ bias, int sel)
{
    extern __shared__ float sm[];
    float* Xs = sm; float* Ws = sm + 256*65;
    __shared__ float bs[64];
    int tid=threadIdx.x;
    int gb=blockIdx.y;
    size_t base=(size_t)blockIdx.x*256;
    const float* X  = sel ? g_message : g_x;
    float*       Out= sel ? g_gh      : g_gi;
    for (int i=tid;i<4096;i+=256){ int k=i>>6, c=i&63; Ws[i]=W[((size_t)(gb*64+c))*64+k]; }
    if (tid<64) bs[tid]=bias[gb*64+tid];
    for (int i=tid;i<16384;i+=256) Xs[((i>>6)*65)+(i&63)] = X[base*64+i];
    __syncthreads();
    u64 acc[32];
    #pragma unroll
    for (int j=0;j<32;j++) acc[j]=pack2(bs[2*j],bs[2*j+1]);
    const float* xr=&Xs[tid*65];
    #pragma unroll 4
    for (int k=0;k<64;k++){
        float xk=xr[k]; u64 x2=pack2(xk,xk);
        const ulonglong2* wr=(const ulonglong2*)&Ws[k*64];
        #pragma unroll
        for (int q=0;q<16;q++){ ulonglong2 w=wr[q]; fma2(acc[2*q],x2,w.x); fma2(acc[2*q+1],x2,w.y); }
    }
    float4* out=(float4*)&Out[(base+tid)*192 + (size_t)gb*64];
    #pragma unroll
    for (int q=0;q<16;q++){
        float2 a=unpack2(acc[2*q]), b=unpack2(acc[2*q+1]);
        out[q]=make_float4(a.x,a.y,b.x,b.y);
    }
}

// ---------------- GRU elementwise + scatter new message ----------------
__global__ void __launch_bounds__(256) k_gru(const int* __restrict__ tgt)
{
    size_t idx=(size_t)blockIdx.x*256+threadIdx.x;   // < EE*64
    size_t e=idx>>6; int f=(int)(idx&63);
    size_t gb=e*192+f;
    float ir=g_gi[gb], iz=g_gi[gb+64], in=g_gi[gb+128];
    float hr=g_gh[gb], hz=g_gh[gb+64], hn=g_gh[gb+128];
    float h=g_message[idx];
    float r=1.f/(1.f+expf(-(ir+hr)));
    float z=1.f/(1.f+expf(-(iz+hz)));
    float n=tanhf(in + r*hn);
    float o=(1.f-z)*n + z*h;
    g_message[idx]=o;
    atomicAdd(&g_agg[(size_t)tgt[e]*64+f], o);
}

// ---------------- nodes_out: agg->relu(@W_aggr+b)->logits->log_softmax + delta ----------------
__global__ void __launch_bounds__(256) k_nodes_out(
    int iter, float* __restrict__ outM, float* __restrict__ outD,
    const float* __restrict__ Wagg, const float* __restrict__ bagg,
    const float* __restrict__ Wout)
{
    __shared__ float Wa[4096]; __shared__ float ba[64]; __shared__ float Wo[192];
    int tid=threadIdx.x;
    for (int i=tid;i<4096;i+=256) Wa[i]=Wagg[i];
    if (tid<64) ba[tid]=bagg[tid];
    for (int i=tid;i<192;i+=256) Wo[i]=Wout[i];  // rows 0..63
    __syncthreads();
    int n=blockIdx.x*256+tid;
    if (n>=NN) return;
    float af[64];
    const float4* ar=(const float4*)&g_agg[(size_t)n*64];
    #pragma unroll
    for (int q=0;q<16;q++){ float4 v=ar[q]; af[4*q]=v.x; af[4*q+1]=v.y; af[4*q+2]=v.z; af[4*q+3]=v.w; }
    u64 acc[32];
    #pragma unroll
    for (int j=0;j<32;j++) acc[j]=pack2(ba[2*j],ba[2*j+1]);
    #pragma unroll 4
    for (int k=0;k<64;k++){
        u64 x2=pack2(af[k],af[k]);
        const ulonglong2* wr=(const ulonglong2*)&Wa[k*64];
        #pragma unroll
        for (int q=0;q<16;q++){ ulonglong2 w=wr[q]; fma2(acc[2*q],x2,w.x); fma2(acc[2*q+1],x2,w.y); }
    }
    float l0=0.f,l1=0.f,l2=0.f;
    #pragma unroll
    for (int j=0;j<32;j++){
        float2 v=unpack2(acc[j]);
        float a0=fmaxf(v.x,0.f), a1=fmaxf(v.y,0.f);
        int k0=4*j*0+2*j, k1=2*j+1;
        l0 += a0*Wo[k0*3+0] + a1*Wo[k1*3+0];
        l1 += a0*Wo[k0*3+1] + a1*Wo[k1*3+1];
        l2 += a0*Wo[k0*3+2] + a1*Wo[k1*3+2];
    }
    l0=fmaxf(l0+g_nf_logit[n*3+0],0.f);
    l1=fmaxf(l1+g_nf_logit[n*3+1],0.f);
    l2=fmaxf(l2+g_nf_logit[n*3+2],0.f);
    float mx=fmaxf(l0,fmaxf(l1,l2));
    float e0=expf(l0-mx), e1=expf(l1-mx), e2=expf(l2-mx);
    float sum=e0+e1+e2, ls=logf(sum);
    size_t ob=(size_t)iter*((size_t)NN*3)+(size_t)n*3;
    outM[ob+0]=l0-mx-ls; outM[ob+1]=l1-mx-ls; outM[ob+2]=l2-mx-ls;
    float p2=e2/sum;
    if (iter>0){
        float d=fabsf(p2-g_prevp[n]);
        atomicMax((int*)&outD[iter-1], __float_as_int(d));
    }
    g_prevp[n]=p2;
}

// ---------------- host ----------------
extern "C" void kernel_launch(void* const* d_in, const int* in_sizes, int n_in,
                              void* d_out, int out_size)
{
    const int*   src  = (const int*)  d_in[0];
    const int*   tgt  = (const int*)  d_in[1];
    const int*   rev  = (const int*)  d_in[2];
    const float* raw  = (const float*)d_in[3];
    const float* prob = (const float*)d_in[4];
    const float* seed = (const float*)d_in[5];
    const float* W_node=(const float*)d_in[6],  *b_node=(const float*)d_in[7];
    const float* W_edge=(const float*)d_in[8],  *b_edge=(const float*)d_in[9];
    const float* W_init=(const float*)d_in[10], *b_init=(const float*)d_in[11];
    const float* W_aggr=(const float*)d_in[12], *b_aggr=(const float*)d_in[13];
    const float* W_out =(const float*)d_in[14], *b_out =(const float*)d_in[15];
    const float* W_me  =(const float*)d_in[16], *b_me  =(const float*)d_in[17];
    const float* W_mp  =(const float*)d_in[18], *b_mp  =(const float*)d_in[19];
    const float* W_ih  =(const float*)d_in[20], *W_hh  =(const float*)d_in[21];
    const float* b_ih  =(const float*)d_in[22], *b_hh  =(const float*)d_in[23];

    float* outM = (float*)d_out;
    float* outD = (float*)d_out + (size_t)5*NN*3;

    cudaFuncSetAttribute(k_me,   cudaFuncAttributeMaxDynamicSharedMemorySize, SME_BYTES);
    cudaFuncSetAttribute(k_mp,   cudaFuncAttributeMaxDynamicSharedMemorySize, SME_BYTES);
    cudaFuncSetAttribute(k_gate, cudaFuncAttributeMaxDynamicSharedMemorySize, SME_BYTES);

    void* aggPtr = 0;
    cudaGetSymbolAddress(&aggPtr, g_agg);

    cudaMemsetAsync(aggPtr, 0, (size_t)NN*64*sizeof(float));
    cudaMemsetAsync(outD, 0, 4*sizeof(float));

    k_node<<<NB_N,256>>>(prob, seed, W_node, b_node, W_init, b_init, W_out, b_out);
    k_edge_init<<<NB_E,256>>>(raw, src, tgt, W_edge, b_edge, W_init, W_me);
    k_nodes_out<<<NB_N,256>>>(0, outM, outD, W_aggr, b_aggr, W_out);

    for (int l=0; l<4; l++){
        cudaMemsetAsync(aggPtr, 0, (size_t)NN*64*sizeof(float));
        k_me<<<NB_E,256,SME_BYTES>>>(W_me, b_me, tgt);
        k_mp<<<NB_E,256,SME_BYTES>>>(W_mp, b_mp, src, rev);
        k_gate<<<dim3(NB_E,3),256,SME_BYTES>>>(W_ih, b_ih, 0);
        k_gate<<<dim3(NB_E,3),256,SME_BYTES>>>(W_hh, b_hh, 1);
        cudaMemsetAsync(aggPtr, 0, (size_t)NN*64*sizeof(float));
        k_gru<<<(EE*64)/256,256>>>(tgt);
        k_nodes_out<<<NB_N,256>>>(l+1, outM, outD, W_aggr, b_aggr, W_out);
    }
}

// round 5
// speedup vs baseline: 1.0388x; 1.0388x over previous
#include <cuda_runtime.h>

#define NN 50000
#define EE 800000

typedef unsigned long long u64;

// ---------------- f32x2 helpers ----------------
__device__ __forceinline__ void fma2(u64 &c, u64 a, u64 b){
    asm("fma.rn.f32x2 %0, %1, %2, %0;" : "+l"(c) : "l"(a), "l"(b));
}
__device__ __forceinline__ u64 pack2(float x, float y){
    u64 r; asm("mov.b64 %0, {%1, %2};" : "=l"(r) : "f"(x), "f"(y)); return r;
}
__device__ __forceinline__ float2 unpack2(u64 v){
    float2 r; asm("mov.b64 {%0, %1}, %2;" : "=f"(r.x), "=f"(r.y) : "l"(v)); return r;
}
__device__ __forceinline__ float sigf(float x){ return 1.f/(1.f+__expf(-x)); }

// ---------------- scratch ----------------
__device__ float g_node_pre[(size_t)NN*64];
__device__ float g_nf_logit[(size_t)NN*3];
__device__ float g_prevp[NN];
__device__ float g_agg[(size_t)NN*64];
__device__ float g_contrib[(size_t)EE*64];
__device__ float g_message[(size_t)EE*64];
__device__ float g_m[(size_t)EE*64];
__device__ float g_x[(size_t)EE*64];
__device__ float g_gi[(size_t)EE*192];   // 3 planes of [EE][64]
__device__ float g_gh[(size_t)EE*192];
__device__ int   g_deg[NN];
__device__ int   g_rowptr[NN+1];
__device__ int   g_cursor[NN];
__device__ int   g_eid[EE];

#define DSM 84224   // (16640 + 4352 + 64) * 4  == (8320+8320+4352+64)*4

// ---------------- GEMM core: thread = (warp w: cols 16w..16w+15) x (lane: edges lane+32j) ----------------
template<int NJ>
__device__ __forceinline__ void gemm_core(const float* Xs, const float* Ws, const float* bs,
                                          int w, int lane, u64 (&acc)[NJ][8])
{
    const int c0 = w*16;
    #pragma unroll
    for (int j=0;j<NJ;j++)
        #pragma unroll
        for (int q=0;q<8;q++) acc[j][q]=pack2(bs[c0+2*q],bs[c0+2*q+1]);
    #pragma unroll 2
    for (int k=0;k<64;k++){
        const ulonglong2* wp=(const ulonglong2*)(Ws + k*68 + c0);
        ulonglong2 a0=wp[0],a1=wp[1],a2=wp[2],a3=wp[3];
        u64 w8[8]={a0.x,a0.y,a1.x,a1.y,a2.x,a2.y,a3.x,a3.y};
        #pragma unroll
        for (int j=0;j<NJ;j++){
            float xk = Xs[(lane+32*j)*65 + k];
            u64 x2 = pack2(xk,xk);
            #pragma unroll
            for (int q=0;q<8;q++) fma2(acc[j][q],x2,w8[q]);
        }
    }
}

template<int NJ>
__device__ __forceinline__ void acc_to_os(float* Os,int w,int lane,u64 (&acc)[NJ][8]){
    const int c0=w*16;
    #pragma unroll
    for (int j=0;j<NJ;j++){
        float* row=&Os[(lane+32*j)*65 + c0];
        #pragma unroll
        for (int q=0;q<8;q++){ float2 v=unpack2(acc[j][q]); row[2*q]=v.x; row[2*q+1]=v.y; }
    }
}

// ---------------- CSR build ----------------
__global__ void __launch_bounds__(256) k_hist(const int* __restrict__ tgt){
    int e=blockIdx.x*256+threadIdx.x;
    atomicAdd(&g_deg[tgt[e]],1);
}
__global__ void __launch_bounds__(1024) k_scan(){
    __shared__ int wsum[32];
    __shared__ int carry_s;
    int t=threadIdx.x, lane=t&31, wid=t>>5;
    if (t==0){ g_rowptr[0]=0; carry_s=0; }
    __syncthreads();
    for (int base=0; base<NN; base+=1024){
        int i=base+t;
        int v=(i<NN)? g_deg[i] : 0;
        int s=v;
        #pragma unroll
        for (int o=1;o<32;o<<=1){ int u=__shfl_up_sync(0xffffffffu,s,o); if(lane>=o) s+=u; }
        if (lane==31) wsum[wid]=s;
        __syncthreads();
        if (wid==0){
            int ws=wsum[lane];
            #pragma unroll
            for (int o=1;o<32;o<<=1){ int u=__shfl_up_sync(0xffffffffu,ws,o); if(lane>=o) ws+=u; }
            wsum[lane]=ws;
        }
        __syncthreads();
        int off=(wid>0)? wsum[wid-1] : 0;
        int inc=s+off+carry_s;
        if (i<NN){ g_rowptr[i+1]=inc; g_cursor[i]=inc-v; }
        __syncthreads();
        if (t==1023) carry_s=inc;
        __syncthreads();
    }
}
__global__ void __launch_bounds__(256) k_fill(const int* __restrict__ tgt){
    int e=blockIdx.x*256+threadIdx.x;
    int p=atomicAdd(&g_cursor[tgt[e]],1);
    g_eid[p]=e;
}

// ---------------- segment sum by gather: agg[n] = sum over in-edges of S ----------------
__global__ void __launch_bounds__(256) k_gather(const float* __restrict__ S){
    int node=blockIdx.x*4+(threadIdx.x>>6);
    int f=threadIdx.x&63;
    int s=g_rowptr[node], e=g_rowptr[node+1];
    float a=0.f;
    for (int i=s;i<e;i++){
        int eid=__ldg(&g_eid[i]);
        a += __ldg(&S[(size_t)eid*64+f]);
    }
    g_agg[(size_t)node*64+f]=a;
}

// ---------------- per-node precompute (unchanged from R3) ----------------
__global__ void __launch_bounds__(256) k_node(
    const float* __restrict__ prob, const float* __restrict__ seed,
    const float* __restrict__ W_node, const float* __restrict__ b_node,
    const float* __restrict__ W_init, const float* __restrict__ b_init,
    const float* __restrict__ W_out,  const float* __restrict__ b_out)
{
    __shared__ float Wi[4096];
    __shared__ float Wn0[64], Wn1[64], bn[64], bi[64], Wo[192], bo[3];
    int tid = threadIdx.x;
    for (int i=tid;i<4096;i+=256) Wi[i]=W_init[i];
    if (tid<64){ Wn0[tid]=W_node[tid]; Wn1[tid]=W_node[64+tid]; bn[tid]=b_node[tid]; bi[tid]=b_init[tid]; }
    for (int i=tid;i<192;i+=256) Wo[i]=W_out[192+i];
    if (tid<3) bo[tid]=b_out[tid];
    __syncthreads();
    int n = blockIdx.x*256 + tid;
    if (n >= NN) return;
    float p = prob[n], s = seed[n];
    u64 acc[32];
    #pragma unroll
    for (int j=0;j<32;j++) acc[j]=pack2(bi[2*j],bi[2*j+1]);
    float l0=bo[0], l1=bo[1], l2=bo[2];
    #pragma unroll 4
    for (int k=0;k<64;k++){
        float nf = fmaxf(fmaf(p,Wn0[k],fmaf(s,Wn1[k],bn[k])), 0.f);
        u64 x2 = pack2(nf,nf);
        const ulonglong2* wr = (const ulonglong2*)&Wi[k*64];
        #pragma unroll
        for (int q=0;q<16;q++){ ulonglong2 w=wr[q]; fma2(acc[2*q],x2,w.x); fma2(acc[2*q+1],x2,w.y); }
        l0 = fmaf(nf,Wo[k*3],l0); l1 = fmaf(nf,Wo[k*3+1],l1); l2 = fmaf(nf,Wo[k*3+2],l2);
    }
    float4* outp = (float4*)&g_node_pre[(size_t)n*64];
    #pragma unroll
    for (int q=0;q<16;q++){ float2 a=unpack2(acc[2*q]); float2 b=unpack2(acc[2*q+1]); outp[q]=make_float4(a.x,a.y,b.x,b.y); }
    g_nf_logit[n*3]=l0; g_nf_logit[n*3+1]=l1; g_nf_logit[n*3+2]=l2;
}

// ---------------- edge init: message + contrib (two GEMM passes, TE=256) ----------------
__global__ void __launch_bounds__(128,2) k_edge_init(
    const float* __restrict__ raw, const int* __restrict__ src,
    const float* __restrict__ W_edge, const float* __restrict__ b_edge,
    const float* __restrict__ W_init, const float* __restrict__ W_me)
{
    extern __shared__ float sm[];
    float* Xs=sm; float* Ws=sm+16640; float* bs=Ws+4352;
    __shared__ float we[64], be[64], rawv[256];
    __shared__ int srcs[256];
    int tid=threadIdx.x, w=tid>>5, lane=tid&31;
    size_t base=(size_t)blockIdx.x*256;
    if (tid<64){ we[tid]=W_edge[tid]; be[tid]=b_edge[tid]; bs[tid]=0.f; }
    for (int i=tid;i<256;i+=128){ rawv[i]=raw[base+i]; srcs[i]=src[base+i]; }
    for (int i=tid;i<4096;i+=128) Ws[(i>>6)*68+(i&63)]=W_init[4096+i];
    __syncthreads();
    for (int i=tid;i<16384;i+=128){ int e=i>>6,f=i&63; Xs[e*65+f]=fmaxf(fmaf(rawv[e],we[f],be[f]),0.f); }
    __syncthreads();
    u64 acc[8][8];
    gemm_core<8>(Xs,Ws,bs,w,lane,acc);
    __syncthreads();
    acc_to_os<8>(Xs,w,lane,acc);
    __syncthreads();
    for (int i=tid;i<16384;i+=128){
        int e=i>>6, f=i&63;
        float v=Xs[e*65+f] + __ldg(&g_node_pre[(size_t)srcs[e]*64+f]);
        g_message[base*64+i]=fmaxf(v,0.f);
    }
    __syncthreads();
    // pass 2: contrib = ef @ W_me[64:128]
    for (int i=tid;i<4096;i+=128) Ws[(i>>6)*68+(i&63)]=W_me[4096+i];
    for (int i=tid;i<16384;i+=128){ int e=i>>6,f=i&63; Xs[e*65+f]=fmaxf(fmaf(rawv[e],we[f],be[f]),0.f); }
    __syncthreads();
    gemm_core<8>(Xs,Ws,bs,w,lane,acc);
    __syncthreads();
    acc_to_os<8>(Xs,w,lane,acc);
    __syncthreads();
    for (int i=tid;i<16384;i+=128) g_contrib[base*64+i]=Xs[(i>>6)*65+(i&63)];
}

// ---------------- m = relu(message @ W_me[0:64] + contrib + b_me) ----------------
__global__ void __launch_bounds__(128,2) k_me(const float* __restrict__ W, const float* __restrict__ b)
{
    extern __shared__ float sm[];
    float* Xs=sm; float* Ws=sm+16640; float* bs=Ws+4352;
    int tid=threadIdx.x, w=tid>>5, lane=tid&31;
    size_t base=(size_t)blockIdx.x*256;
    for (int i=tid;i<4096;i+=128) Ws[(i>>6)*68+(i&63)]=W[i];
    if (tid<64) bs[tid]=b[tid];
    for (int i=tid;i<16384;i+=128) Xs[(i>>6)*65+(i&63)]=g_message[base*64+i];
    __syncthreads();
    u64 acc[8][8];
    gemm_core<8>(Xs,Ws,bs,w,lane,acc);
    __syncthreads();
    acc_to_os<8>(Xs,w,lane,acc);
    __syncthreads();
    for (int i=tid;i<16384;i+=128){
        float v=Xs[(i>>6)*65+(i&63)] + g_contrib[base*64+i];
        g_m[base*64+i]=fmaxf(v,0.f);
    }
}

// ---------------- x = relu((agg[src] - m[rev]) @ W_mp + b_mp) ----------------
__global__ void __launch_bounds__(128,2) k_mp(
    const float* __restrict__ W, const float* __restrict__ b,
    const int* __restrict__ src, const int* __restrict__ rev)
{
    extern __shared__ float sm[];
    float* Xs=sm; float* Ws=sm+16640; float* bs=Ws+4352;
    __shared__ int srcs[256], revs[256];
    int tid=threadIdx.x, w=tid>>5, lane=tid&31;
    size_t base=(size_t)blockIdx.x*256;
    for (int i=tid;i<256;i+=128){ srcs[i]=src[base+i]; revs[i]=rev[base+i]; }
    for (int i=tid;i<4096;i+=128) Ws[(i>>6)*68+(i&63)]=W[i];
    if (tid<64) bs[tid]=b[tid];
    __syncthreads();
    for (int i=tid;i<16384;i+=128){
        int e=i>>6, f=i&63;
        Xs[e*65+f] = __ldg(&g_agg[(size_t)srcs[e]*64+f]) - __ldg(&g_m[(size_t)revs[e]*64+f]);
    }
    __syncthreads();
    u64 acc[8][8];
    gemm_core<8>(Xs,Ws,bs,w,lane,acc);
    __syncthreads();
    acc_to_os<8>(Xs,w,lane,acc);
    __syncthreads();
    for (int i=tid;i<16384;i+=128) g_x[base*64+i]=fmaxf(Xs[(i>>6)*65+(i&63)],0.f);
}

// ---------------- gates: Og[gb][e][c] = X[e] . Wg[(64gb+c),:] + bg   (TE=128, 3 gb passes) ----------------
__global__ void __launch_bounds__(128,2) k_gate(
    const float* __restrict__ Wg, const float* __restrict__ bg,
    const float* __restrict__ Xg, float* __restrict__ Og)
{
    extern __shared__ float sm[];
    float* Xs=sm;            // 128*65
    float* Os=sm+8320;       // 128*65
    float* Ws=sm+16640;      // 64*68
    float* bs=Ws+4352;
    int tid=threadIdx.x, w=tid>>5, lane=tid&31;
    size_t base=(size_t)blockIdx.x*128;
    for (int i=tid;i<8192;i+=128) Xs[(i>>6)*65+(i&63)]=Xg[base*64+i];
    for (int gb=0; gb<3; gb++){
        __syncthreads();
        for (int i=tid;i<4096;i+=128){ int c=i>>6, k=i&63; Ws[k*68+c]=Wg[gb*4096+i]; }
        if (tid<64) bs[tid]=bg[gb*64+tid];
        __syncthreads();
        u64 acc[4][8];
        gemm_core<4>(Xs,Ws,bs,w,lane,acc);
        acc_to_os<4>(Os,w,lane,acc);
        __syncthreads();
        float* outp = Og + (size_t)gb*((size_t)EE*64) + base*64;
        for (int i=tid;i<8192;i+=128) outp[i]=Os[(i>>6)*65+(i&63)];
    }
}

// ---------------- GRU elementwise (float4, plane layout) ----------------
__global__ void __launch_bounds__(256) k_gru(){
    size_t idx=((size_t)blockIdx.x*256+threadIdx.x)*4;
    const size_t P=(size_t)EE*64;
    float4 ir=*(const float4*)&g_gi[idx];
    float4 iz=*(const float4*)&g_gi[P+idx];
    float4 in4=*(const float4*)&g_gi[2*P+idx];
    float4 hr=*(const float4*)&g_gh[idx];
    float4 hz=*(const float4*)&g_gh[P+idx];
    float4 hn=*(const float4*)&g_gh[2*P+idx];
    float4 h=*(const float4*)&g_message[idx];
    float4 o;
    {
        float r=sigf(ir.x+hr.x), z=sigf(iz.x+hz.x);
        float n=2.f*sigf(2.f*(in4.x+r*hn.x))-1.f;
        o.x=(1.f-z)*n+z*h.x;
    }{
        float r=sigf(ir.y+hr.y), z=sigf(iz.y+hz.y);
        float n=2.f*sigf(2.f*(in4.y+r*hn.y))-1.f;
        o.y=(1.f-z)*n+z*h.y;
    }{
        float r=sigf(ir.z+hr.z), z=sigf(iz.z+hz.z);
        float n=2.f*sigf(2.f*(in4.z+r*hn.z))-1.f;
        o.z=(1.f-z)*n+z*h.z;
    }{
        float r=sigf(ir.w+hr.w), z=sigf(iz.w+hz.w);
        float n=2.f*sigf(2.f*(in4.w+r*hn.w))-1.f;
        o.w=(1.f-z)*n+z*h.w;
    }
    *(float4*)&g_message[idx]=o;
}

// ---------------- nodes_out (unchanged from R3, reads g_agg) ----------------
__global__ void __launch_bounds__(256) k_nodes_out(
    int iter, float* __restrict__ outM, float* __restrict__ outD,
    const float* __restrict__ Wagg, const float* __restrict__ bagg,
    const float* __restrict__ Wout)
{
    __shared__ float Wa[4096]; __shared__ float ba[64]; __shared__ float Wo[192];
    int tid=threadIdx.x;
    for (int i=tid;i<4096;i+=256) Wa[i]=Wagg[i];
    if (tid<64) ba[tid]=bagg[tid];
    for (int i=tid;i<192;i+=256) Wo[i]=Wout[i];
    __syncthreads();
    int n=blockIdx.x*256+tid;
    if (n>=NN) return;
    float af[64];
    const float4* ar=(const float4*)&g_agg[(size_t)n*64];
    #pragma unroll
    for (int q=0;q<16;q++){ float4 v=ar[q]; af[4*q]=v.x; af[4*q+1]=v.y; af[4*q+2]=v.z; af[4*q+3]=v.w; }
    u64 acc[32];
    #pragma unroll
    for (int j=0;j<32;j++) acc[j]=pack2(ba[2*j],ba[2*j+1]);
    #pragma unroll 4
    for (int k=0;k<64;k++){
        u64 x2=pack2(af[k],af[k]);
        const ulonglong2* wr=(const ulonglong2*)&Wa[k*64];
        #pragma unroll
        for (int q=0;q<16;q++){ ulonglong2 w=wr[q]; fma2(acc[2*q],x2,w.x); fma2(acc[2*q+1],x2,w.y); }
    }
    float l0=0.f,l1=0.f,l2=0.f;
    #pragma unroll
    for (int j=0;j<32;j++){
        float2 v=unpack2(acc[j]);
        float a0=fmaxf(v.x,0.f), a1=fmaxf(v.y,0.f);
        int k0=2*j, k1=2*j+1;
        l0 += a0*Wo[k0*3+0] + a1*Wo[k1*3+0];
        l1 += a0*Wo[k0*3+1] + a1*Wo[k1*3+1];
        l2 += a0*Wo[k0*3+2] + a1*Wo[k1*3+2];
    }
    l0=fmaxf(l0+g_nf_logit[n*3+0],0.f);
    l1=fmaxf(l1+g_nf_logit[n*3+1],0.f);
    l2=fmaxf(l2+g_nf_logit[n*3+2],0.f);
    float mx=fmaxf(l0,fmaxf(l1,l2));
    float e0=expf(l0-mx), e1=expf(l1-mx), e2=expf(l2-mx);
    float sum=e0+e1+e2, ls=logf(sum);
    size_t ob=(size_t)iter*((size_t)NN*3)+(size_t)n*3;
    outM[ob+0]=l0-mx-ls; outM[ob+1]=l1-mx-ls; outM[ob+2]=l2-mx-ls;
    float p2=e2/sum;
    if (iter>0){
        float d=fabsf(p2-g_prevp[n]);
        atomicMax((int*)&outD[iter-1], __float_as_int(d));
    }
    g_prevp[n]=p2;
}

// ---------------- host ----------------
extern "C" void kernel_launch(void* const* d_in, const int* in_sizes, int n_in,
                              void* d_out, int out_size)
{
    const int*   src  = (const int*)  d_in[0];
    const int*   tgt  = (const int*)  d_in[1];
    const int*   rev  = (const int*)  d_in[2];
    const float* raw  = (const float*)d_in[3];
    const float* prob = (const float*)d_in[4];
    const float* seed = (const float*)d_in[5];
    const float* W_node=(const float*)d_in[6],  *b_node=(const float*)d_in[7];
    const float* W_edge=(const float*)d_in[8],  *b_edge=(const float*)d_in[9];
    const float* W_init=(const float*)d_in[10], *b_init=(const float*)d_in[11];
    const float* W_aggr=(const float*)d_in[12], *b_aggr=(const float*)d_in[13];
    const float* W_out =(const float*)d_in[14], *b_out =(const float*)d_in[15];
    const float* W_me  =(const float*)d_in[16], *b_me  =(const float*)d_in[17];
    const float* W_mp  =(const float*)d_in[18], *b_mp  =(const float*)d_in[19];
    const float* W_ih  =(const float*)d_in[20], *W_hh  =(const float*)d_in[21];
    const float* b_ih  =(const float*)d_in[22], *b_hh  =(const float*)d_in[23];

    float* outM = (float*)d_out;
    float* outD = (float*)d_out + (size_t)5*NN*3;

    cudaFuncSetAttribute(k_edge_init, cudaFuncAttributeMaxDynamicSharedMemorySize, DSM);
    cudaFuncSetAttribute(k_me,        cudaFuncAttributeMaxDynamicSharedMemorySize, DSM);
    cudaFuncSetAttribute(k_mp,        cudaFuncAttributeMaxDynamicSharedMemorySize, DSM);
    cudaFuncSetAttribute(k_gate,      cudaFuncAttributeMaxDynamicSharedMemorySize, DSM);

    void *degPtr=0, *msgPtr=0, *mPtr=0, *xPtr=0, *giPtr=0, *ghPtr=0;
    cudaGetSymbolAddress(&degPtr, g_deg);
    cudaGetSymbolAddress(&msgPtr, g_message);
    cudaGetSymbolAddress(&mPtr,   g_m);
    cudaGetSymbolAddress(&xPtr,   g_x);
    cudaGetSymbolAddress(&giPtr,  g_gi);
    cudaGetSymbolAddress(&ghPtr,  g_gh);

    cudaMemsetAsync(degPtr, 0, NN*sizeof(int));
    cudaMemsetAsync(outD, 0, 4*sizeof(float));

    k_hist<<<EE/256,256>>>(tgt);
    k_scan<<<1,1024>>>();
    k_fill<<<EE/256,256>>>(tgt);

    k_node<<<(NN+255)/256,256>>>(prob, seed, W_node, b_node, W_init, b_init, W_out, b_out);
    k_edge_init<<<EE/256,128,DSM>>>(raw, src, W_edge, b_edge, W_init, W_me);
    k_gather<<<NN/4,256>>>((const float*)msgPtr);
    k_nodes_out<<<(NN+255)/256,256>>>(0, outM, outD, W_aggr, b_aggr, W_out);

    for (int l=0; l<4; l++){
        k_me<<<EE/256,128,DSM>>>(W_me, b_me);
        k_gather<<<NN/4,256>>>((const float*)mPtr);
        k_mp<<<EE/256,128,DSM>>>(W_mp, b_mp, src, rev);
        k_gate<<<EE/128,128,DSM>>>(W_ih, b_ih, (const float*)xPtr, (float*)giPtr);
        k_gate<<<EE/128,128,DSM>>>(W_hh, b_hh, (const float*)msgPtr, (float*)ghPtr);
        k_gru<<<(EE*64/4)/256,256>>>();
        k_gather<<<NN/4,256>>>((const float*)msgPtr);
        k_nodes_out<<<(NN+255)/256,256>>>(l+1, outM, outD, W_aggr, b_aggr, W_out);
    }
}

// round 6
// speedup vs baseline: 1.4168x; 1.3640x over previous
#include <cuda_runtime.h>

#define NN 50000
#define EE 800000

typedef unsigned long long u64;

// ---------------- f32x2 helpers ----------------
__device__ __forceinline__ void fma2(u64 &c, u64 a, u64 b){
    asm("fma.rn.f32x2 %0, %1, %2, %0;" : "+l"(c) : "l"(a), "l"(b));
}
__device__ __forceinline__ u64 pack2(float x, float y){
    u64 r; asm("mov.b64 %0, {%1, %2};" : "=l"(r) : "f"(x), "f"(y)); return r;
}
__device__ __forceinline__ float2 unpack2(u64 v){
    float2 r; asm("mov.b64 {%0, %1}, %2;" : "=f"(r.x), "=f"(r.y) : "l"(v)); return r;
}
__device__ __forceinline__ float sigf(float x){ return 1.f/(1.f+__expf(-x)); }

// ---------------- scratch ----------------
__device__ float g_node_pre[(size_t)NN*64];
__device__ float g_nf_logit[(size_t)NN*3];
__device__ float g_prevp[NN];
__device__ float g_agg[(size_t)NN*64];
__device__ float g_contrib[(size_t)EE*64];
__device__ float g_message[(size_t)EE*64];
__device__ float g_m[(size_t)EE*64];
__device__ float g_x[(size_t)EE*64];
__device__ float g_gi[(size_t)EE*192];   // 3 planes of [EE][64]
__device__ float g_gh[(size_t)EE*192];
__device__ int   g_deg[NN];
__device__ int   g_rowptr[NN+1];
__device__ int   g_cursor[NN];
__device__ int   g_eid[EE];

// smem for all GEMM kernels: 12736 floats = 50944 bytes
//  gemm64: Xs 128*65 (8320) + Ws 64*68 (4352) + bs 64
//  gate:   Xs 64*65 (4160) + Os 64*65 (4160) + Ws 4352 + bs 64
#define DSM 50944

// ---------------- GEMM core: warp w -> cols 16w..16w+15; lane -> edges lane+32j ----------------
template<int NJ>
__device__ __forceinline__ void gemm_core(const float* Xs, const float* Ws, const float* bs,
                                          int w, int lane, u64 (&acc)[NJ][8])
{
    const int c0 = w*16;
    #pragma unroll
    for (int j=0;j<NJ;j++)
        #pragma unroll
        for (int q=0;q<8;q++) acc[j][q]=pack2(bs[c0+2*q],bs[c0+2*q+1]);
    #pragma unroll 2
    for (int k=0;k<64;k++){
        const ulonglong2* wp=(const ulonglong2*)(Ws + k*68 + c0);
        ulonglong2 a0=wp[0],a1=wp[1],a2=wp[2],a3=wp[3];
        u64 w8[8]={a0.x,a0.y,a1.x,a1.y,a2.x,a2.y,a3.x,a3.y};
        #pragma unroll
        for (int j=0;j<NJ;j++){
            float xk = Xs[(lane+32*j)*65 + k];
            u64 x2 = pack2(xk,xk);
            #pragma unroll
            for (int q=0;q<8;q++) fma2(acc[j][q],x2,w8[q]);
        }
    }
}

template<int NJ>
__device__ __forceinline__ void acc_to_os(float* Os,int w,int lane,u64 (&acc)[NJ][8]){
    const int c0=w*16;
    #pragma unroll
    for (int j=0;j<NJ;j++){
        float* row=&Os[(lane+32*j)*65 + c0];
        #pragma unroll
        for (int q=0;q<8;q++){ float2 v=unpack2(acc[j][q]); row[2*q]=v.x; row[2*q+1]=v.y; }
    }
}

// ---------------- CSR build ----------------
__global__ void __launch_bounds__(256) k_hist(const int* __restrict__ tgt){
    int e=blockIdx.x*256+threadIdx.x;
    atomicAdd(&g_deg[tgt[e]],1);
}
__global__ void __launch_bounds__(1024) k_scan(){
    __shared__ int wsum[32];
    __shared__ int carry_s;
    int t=threadIdx.x, lane=t&31, wid=t>>5;
    if (t==0){ g_rowptr[0]=0; carry_s=0; }
    __syncthreads();
    for (int base=0; base<NN; base+=1024){
        int i=base+t;
        int v=(i<NN)? g_deg[i] : 0;
        int s=v;
        #pragma unroll
        for (int o=1;o<32;o<<=1){ int u=__shfl_up_sync(0xffffffffu,s,o); if(lane>=o) s+=u; }
        if (lane==31) wsum[wid]=s;
        __syncthreads();
        if (wid==0){
            int ws=wsum[lane];
            #pragma unroll
            for (int o=1;o<32;o<<=1){ int u=__shfl_up_sync(0xffffffffu,ws,o); if(lane>=o) ws+=u; }
            wsum[lane]=ws;
        }
        __syncthreads();
        int off=(wid>0)? wsum[wid-1] : 0;
        int inc=s+off+carry_s;
        if (i<NN){ g_rowptr[i+1]=inc; g_cursor[i]=inc-v; }
        __syncthreads();
        if (t==1023) carry_s=inc;
        __syncthreads();
    }
}
__global__ void __launch_bounds__(256) k_fill(const int* __restrict__ tgt){
    int e=blockIdx.x*256+threadIdx.x;
    int p=atomicAdd(&g_cursor[tgt[e]],1);
    g_eid[p]=e;
}

// ---------------- segment sum by gather ----------------
__global__ void __launch_bounds__(256) k_gather(const float* __restrict__ S){
    int node=blockIdx.x*4+(threadIdx.x>>6);
    int f=threadIdx.x&63;
    int s=g_rowptr[node], e=g_rowptr[node+1];
    float a=0.f;
    for (int i=s;i<e;i++){
        int eid=__ldg(&g_eid[i]);
        a += __ldg(&S[(size_t)eid*64+f]);
    }
    g_agg[(size_t)node*64+f]=a;
}

// ---------------- per-node precompute ----------------
__global__ void __launch_bounds__(256) k_node(
    const float* __restrict__ prob, const float* __restrict__ seed,
    const float* __restrict__ W_node, const float* __restrict__ b_node,
    const float* __restrict__ W_init, const float* __restrict__ b_init,
    const float* __restrict__ W_out,  const float* __restrict__ b_out)
{
    __shared__ float Wi[4096];
    __shared__ float Wn0[64], Wn1[64], bn[64], bi[64], Wo[192], bo[3];
    int tid = threadIdx.x;
    for (int i=tid;i<4096;i+=256) Wi[i]=W_init[i];
    if (tid<64){ Wn0[tid]=W_node[tid]; Wn1[tid]=W_node[64+tid]; bn[tid]=b_node[tid]; bi[tid]=b_init[tid]; }
    for (int i=tid;i<192;i+=256) Wo[i]=W_out[192+i];
    if (tid<3) bo[tid]=b_out[tid];
    __syncthreads();
    int n = blockIdx.x*256 + tid;
    if (n >= NN) return;
    float p = prob[n], s = seed[n];
    u64 acc[32];
    #pragma unroll
    for (int j=0;j<32;j++) acc[j]=pack2(bi[2*j],bi[2*j+1]);
    float l0=bo[0], l1=bo[1], l2=bo[2];
    #pragma unroll 4
    for (int k=0;k<64;k++){
        float nf = fmaxf(fmaf(p,Wn0[k],fmaf(s,Wn1[k],bn[k])), 0.f);
        u64 x2 = pack2(nf,nf);
        const ulonglong2* wr = (const ulonglong2*)&Wi[k*64];
        #pragma unroll
        for (int q=0;q<16;q++){ ulonglong2 w=wr[q]; fma2(acc[2*q],x2,w.x); fma2(acc[2*q+1],x2,w.y); }
        l0 = fmaf(nf,Wo[k*3],l0); l1 = fmaf(nf,Wo[k*3+1],l1); l2 = fmaf(nf,Wo[k*3+2],l2);
    }
    float4* outp = (float4*)&g_node_pre[(size_t)n*64];
    #pragma unroll
    for (int q=0;q<16;q++){ float2 a=unpack2(acc[2*q]); float2 b=unpack2(acc[2*q+1]); outp[q]=make_float4(a.x,a.y,b.x,b.y); }
    g_nf_logit[n*3]=l0; g_nf_logit[n*3+1]=l1; g_nf_logit[n*3+2]=l2;
}

// ---------------- edge init: message + contrib (TE=128, NJ=4) ----------------
__global__ void __launch_bounds__(128,3) k_edge_init(
    const float* __restrict__ raw, const int* __restrict__ src,
    const float* __restrict__ W_edge, const float* __restrict__ b_edge,
    const float* __restrict__ W_init, const float* __restrict__ W_me)
{
    extern __shared__ float sm[];
    float* Xs=sm; float* Ws=sm+8320; float* bs=Ws+4352;
    __shared__ float we[64], be[64], rawv[128];
    __shared__ int srcs[128];
    int tid=threadIdx.x, w=tid>>5, lane=tid&31;
    size_t base=(size_t)blockIdx.x*128;
    if (tid<64){ we[tid]=W_edge[tid]; be[tid]=b_edge[tid]; bs[tid]=0.f; }
    rawv[tid]=raw[base+tid]; srcs[tid]=src[base+tid];
    for (int i=tid;i<4096;i+=128) Ws[(i>>6)*68+(i&63)]=W_init[4096+i];
    __syncthreads();
    for (int i=tid;i<8192;i+=128){ int e=i>>6,f=i&63; Xs[e*65+f]=fmaxf(fmaf(rawv[e],we[f],be[f]),0.f); }
    __syncthreads();
    u64 acc[4][8];
    gemm_core<4>(Xs,Ws,bs,w,lane,acc);
    __syncthreads();
    acc_to_os<4>(Xs,w,lane,acc);
    __syncthreads();
    for (int i=tid;i<8192;i+=128){
        int e=i>>6, f=i&63;
        float v=Xs[e*65+f] + __ldg(&g_node_pre[(size_t)srcs[e]*64+f]);
        g_message[base*64+i]=fmaxf(v,0.f);
    }
    __syncthreads();
    // pass 2: contrib = ef @ W_me[64:128]
    for (int i=tid;i<4096;i+=128) Ws[(i>>6)*68+(i&63)]=W_me[4096+i];
    __syncthreads();
    for (int i=tid;i<8192;i+=128){ int e=i>>6,f=i&63; Xs[e*65+f]=fmaxf(fmaf(rawv[e],we[f],be[f]),0.f); }
    __syncthreads();
    gemm_core<4>(Xs,Ws,bs,w,lane,acc);
    __syncthreads();
    acc_to_os<4>(Xs,w,lane,acc);
    __syncthreads();
    for (int i=tid;i<8192;i+=128) g_contrib[base*64+i]=Xs[(i>>6)*65+(i&63)];
}

// ---------------- m = relu(message @ W_me[0:64] + contrib + b_me) ----------------
__global__ void __launch_bounds__(128,3) k_me(const float* __restrict__ W, const float* __restrict__ b)
{
    extern __shared__ float sm[];
    float* Xs=sm; float* Ws=sm+8320; float* bs=Ws+4352;
    int tid=threadIdx.x, w=tid>>5, lane=tid&31;
    size_t base=(size_t)blockIdx.x*128;
    for (int i=tid;i<4096;i+=128) Ws[(i>>6)*68+(i&63)]=W[i];
    if (tid<64) bs[tid]=b[tid];
    for (int i=tid;i<8192;i+=128) Xs[(i>>6)*65+(i&63)]=g_message[base*64+i];
    __syncthreads();
    u64 acc[4][8];
    gemm_core<4>(Xs,Ws,bs,w,lane,acc);
    __syncthreads();
    acc_to_os<4>(Xs,w,lane,acc);
    __syncthreads();
    for (int i=tid;i<8192;i+=128){
        float v=Xs[(i>>6)*65+(i&63)] + g_contrib[base*64+i];
        g_m[base*64+i]=fmaxf(v,0.f);
    }
}

// ---------------- x = relu((agg[src] - m[rev]) @ W_mp + b_mp) ----------------
__global__ void __launch_bounds__(128,3) k_mp(
    const float* __restrict__ W, const float* __restrict__ b,
    const int* __restrict__ src, const int* __restrict__ rev)
{
    extern __shared__ float sm[];
    float* Xs=sm; float* Ws=sm+8320; float* bs=Ws+4352;
    __shared__ int srcs[128], revs[128];
    int tid=threadIdx.x, w=tid>>5, lane=tid&31;
    size_t base=(size_t)blockIdx.x*128;
    srcs[tid]=src[base+tid]; revs[tid]=rev[base+tid];
    for (int i=tid;i<4096;i+=128) Ws[(i>>6)*68+(i&63)]=W[i];
    if (tid<64) bs[tid]=b[tid];
    __syncthreads();
    for (int i=tid;i<8192;i+=128){
        int e=i>>6, f=i&63;
        Xs[e*65+f] = __ldg(&g_agg[(size_t)srcs[e]*64+f]) - __ldg(&g_m[(size_t)revs[e]*64+f]);
    }
    __syncthreads();
    u64 acc[4][8];
    gemm_core<4>(Xs,Ws,bs,w,lane,acc);
    __syncthreads();
    acc_to_os<4>(Xs,w,lane,acc);
    __syncthreads();
    for (int i=tid;i<8192;i+=128) g_x[base*64+i]=fmaxf(Xs[(i>>6)*65+(i&63)],0.f);
}

// ---------------- gates: TE=64, NJ=2, 3 gb passes ----------------
__global__ void __launch_bounds__(128,3) k_gate(
    const float* __restrict__ Wg, const float* __restrict__ bg,
    const float* __restrict__ Xg, float* __restrict__ Og)
{
    extern __shared__ float sm[];
    float* Xs=sm;            // 64*65
    float* Os=sm+4160;       // 64*65
    float* Ws=sm+8320;       // 64*68
    float* bs=Ws+4352;
    int tid=threadIdx.x, w=tid>>5, lane=tid&31;
    size_t base=(size_t)blockIdx.x*64;
    for (int i=tid;i<4096;i+=128) Xs[(i>>6)*65+(i&63)]=Xg[base*64+i];
    for (int gb=0; gb<3; gb++){
        __syncthreads();
        for (int i=tid;i<4096;i+=128){ int c=i>>6, k=i&63; Ws[k*68+c]=Wg[gb*4096+i]; }
        if (tid<64) bs[tid]=bg[gb*64+tid];
        __syncthreads();
        u64 acc[2][8];
        gemm_core<2>(Xs,Ws,bs,w,lane,acc);
        acc_to_os<2>(Os,w,lane,acc);
        __syncthreads();
        float* outp = Og + (size_t)gb*((size_t)EE*64) + base*64;
        for (int i=tid;i<4096;i+=128) outp[i]=Os[(i>>6)*65+(i&63)];
    }
}

// ---------------- GRU elementwise (float4, plane layout) ----------------
__global__ void __launch_bounds__(256) k_gru(){
    size_t idx=((size_t)blockIdx.x*256+threadIdx.x)*4;
    const size_t P=(size_t)EE*64;
    float4 ir=*(const float4*)&g_gi[idx];
    float4 iz=*(const float4*)&g_gi[P+idx];
    float4 in4=*(const float4*)&g_gi[2*P+idx];
    float4 hr=*(const float4*)&g_gh[idx];
    float4 hz=*(const float4*)&g_gh[P+idx];
    float4 hn=*(const float4*)&g_gh[2*P+idx];
    float4 h=*(const float4*)&g_message[idx];
    float4 o;
    {
        float r=sigf(ir.x+hr.x), z=sigf(iz.x+hz.x);
        float n=2.f*sigf(2.f*(in4.x+r*hn.x))-1.f;
        o.x=(1.f-z)*n+z*h.x;
    }{
        float r=sigf(ir.y+hr.y), z=sigf(iz.y+hz.y);
        float n=2.f*sigf(2.f*(in4.y+r*hn.y))-1.f;
        o.y=(1.f-z)*n+z*h.y;
    }{
        float r=sigf(ir.z+hr.z), z=sigf(iz.z+hz.z);
        float n=2.f*sigf(2.f*(in4.z+r*hn.z))-1.f;
        o.z=(1.f-z)*n+z*h.z;
    }{
        float r=sigf(ir.w+hr.w), z=sigf(iz.w+hz.w);
        float n=2.f*sigf(2.f*(in4.w+r*hn.w))-1.f;
        o.w=(1.f-z)*n+z*h.w;
    }
    *(float4*)&g_message[idx]=o;
}

// ---------------- nodes_out ----------------
__global__ void __launch_bounds__(256) k_nodes_out(
    int iter, float* __restrict__ outM, float* __restrict__ outD,
    const float* __restrict__ Wagg, const float* __restrict__ bagg,
    const float* __restrict__ Wout)
{
    __shared__ float Wa[4096]; __shared__ float ba[64]; __shared__ float Wo[192];
    int tid=threadIdx.x;
    for (int i=tid;i<4096;i+=256) Wa[i]=Wagg[i];
    if (tid<64) ba[tid]=bagg[tid];
    for (int i=tid;i<192;i+=256) Wo[i]=Wout[i];
    __syncthreads();
    int n=blockIdx.x*256+tid;
    if (n>=NN) return;
    float af[64];
    const float4* ar=(const float4*)&g_agg[(size_t)n*64];
    #pragma unroll
    for (int q=0;q<16;q++){ float4 v=ar[q]; af[4*q]=v.x; af[4*q+1]=v.y; af[4*q+2]=v.z; af[4*q+3]=v.w; }
    u64 acc[32];
    #pragma unroll
    for (int j=0;j<32;j++) acc[j]=pack2(ba[2*j],ba[2*j+1]);
    #pragma unroll 4
    for (int k=0;k<64;k++){
        u64 x2=pack2(af[k],af[k]);
        const ulonglong2* wr=(const ulonglong2*)&Wa[k*64];
        #pragma unroll
        for (int q=0;q<16;q++){ ulonglong2 w=wr[q]; fma2(acc[2*q],x2,w.x); fma2(acc[2*q+1],x2,w.y); }
    }
    float l0=0.f,l1=0.f,l2=0.f;
    #pragma unroll
    for (int j=0;j<32;j++){
        float2 v=unpack2(acc[j]);
        float a0=fmaxf(v.x,0.f), a1=fmaxf(v.y,0.f);
        int k0=2*j, k1=2*j+1;
        l0 += a0*Wo[k0*3+0] + a1*Wo[k1*3+0];
        l1 += a0*Wo[k0*3+1] + a1*Wo[k1*3+1];
        l2 += a0*Wo[k0*3+2] + a1*Wo[k1*3+2];
    }
    l0=fmaxf(l0+g_nf_logit[n*3+0],0.f);
    l1=fmaxf(l1+g_nf_logit[n*3+1],0.f);
    l2=fmaxf(l2+g_nf_logit[n*3+2],0.f);
    float mx=fmaxf(l0,fmaxf(l1,l2));
    float e0=expf(l0-mx), e1=expf(l1-mx), e2=expf(l2-mx);
    float sum=e0+e1+e2, ls=logf(sum);
    size_t ob=(size_t)iter*((size_t)NN*3)+(size_t)n*3;
    outM[ob+0]=l0-mx-ls; outM[ob+1]=l1-mx-ls; outM[ob+2]=l2-mx-ls;
    float p2=e2/sum;
    if (iter>0){
        float d=fabsf(p2-g_prevp[n]);
        atomicMax((int*)&outD[iter-1], __float_as_int(d));
    }
    g_prevp[n]=p2;
}

// ---------------- host ----------------
extern "C" void kernel_launch(void* const* d_in, const int* in_sizes, int n_in,
                              void* d_out, int out_size)
{
    const int*   src  = (const int*)  d_in[0];
    const int*   tgt  = (const int*)  d_in[1];
    const int*   rev  = (const int*)  d_in[2];
    const float* raw  = (const float*)d_in[3];
    const float* prob = (const float*)d_in[4];
    const float* seed = (const float*)d_in[5];
    const float* W_node=(const float*)d_in[6],  *b_node=(const float*)d_in[7];
    const float* W_edge=(const float*)d_in[8],  *b_edge=(const float*)d_in[9];
    const float* W_init=(const float*)d_in[10], *b_init=(const float*)d_in[11];
    const float* W_aggr=(const float*)d_in[12], *b_aggr=(const float*)d_in[13];
    const float* W_out =(const float*)d_in[14], *b_out =(const float*)d_in[15];
    const float* W_me  =(const float*)d_in[16], *b_me  =(const float*)d_in[17];
    const float* W_mp  =(const float*)d_in[18], *b_mp  =(const float*)d_in[19];
    const float* W_ih  =(const float*)d_in[20], *W_hh  =(const float*)d_in[21];
    const float* b_ih  =(const float*)d_in[22], *b_hh  =(const float*)d_in[23];

    float* outM = (float*)d_out;
    float* outD = (float*)d_out + (size_t)5*NN*3;

    cudaFuncSetAttribute(k_edge_init, cudaFuncAttributeMaxDynamicSharedMemorySize, DSM);
    cudaFuncSetAttribute(k_me,        cudaFuncAttributeMaxDynamicSharedMemorySize, DSM);
    cudaFuncSetAttribute(k_mp,        cudaFuncAttributeMaxDynamicSharedMemorySize, DSM);
    cudaFuncSetAttribute(k_gate,      cudaFuncAttributeMaxDynamicSharedMemorySize, DSM);

    void *degPtr=0, *msgPtr=0, *mPtr=0, *xPtr=0, *giPtr=0, *ghPtr=0;
    cudaGetSymbolAddress(&degPtr, g_deg);
    cudaGetSymbolAddress(&msgPtr, g_message);
    cudaGetSymbolAddress(&mPtr,   g_m);
    cudaGetSymbolAddress(&xPtr,   g_x);
    cudaGetSymbolAddress(&giPtr,  g_gi);
    cudaGetSymbolAddress(&ghPtr,  g_gh);

    // launch order arranged so ncu (-s 5 -c 1) captures k_edge_init
    cudaMemsetAsync(degPtr, 0, NN*sizeof(int));                 // 1
    k_hist<<<EE/256,256>>>(tgt);                                // 2
    k_scan<<<1,1024>>>();                                       // 3
    k_fill<<<EE/256,256>>>(tgt);                                // 4
    k_node<<<(NN+255)/256,256>>>(prob, seed, W_node, b_node, W_init, b_init, W_out, b_out); // 5
    k_edge_init<<<EE/128,128,DSM>>>(raw, src, W_edge, b_edge, W_init, W_me);                // 6 (captured)

    cudaMemsetAsync(outD, 0, 4*sizeof(float));
    k_gather<<<NN/4,256>>>((const float*)msgPtr);
    k_nodes_out<<<(NN+255)/256,256>>>(0, outM, outD, W_aggr, b_aggr, W_out);

    for (int l=0; l<4; l++){
        k_me<<<EE/128,128,DSM>>>(W_me, b_me);
        k_gather<<<NN/4,256>>>((const float*)mPtr);
        k_mp<<<EE/128,128,DSM>>>(W_mp, b_mp, src, rev);
        k_gate<<<EE/64,128,DSM>>>(W_ih, b_ih, (const float*)xPtr, (float*)giPtr);
        k_gate<<<EE/64,128,DSM>>>(W_hh, b_hh, (const float*)msgPtr, (float*)ghPtr);
        k_gru<<<(EE*64/4)/256,256>>>();
        k_gather<<<NN/4,256>>>((const float*)msgPtr);
        k_nodes_out<<<(NN+255)/256,256>>>(l+1, outM, outD, W_aggr, b_aggr, W_out);
    }
}